// round 4
// baseline (speedup 1.0000x reference)
#include <cuda_runtime.h>
#include <cstdint>

#define NC     8                 // cluster size (CTAs)
#define T      256               // threads per CTA
#define NWARP  (T / 32)          // 8 warps
#define VPT    8                 // elements per thread: NC*T*VPT = 16384

__device__ __forceinline__ uint32_t ctarank() {
    uint32_t r; asm("mov.u32 %0, %%cluster_ctarank;" : "=r"(r)); return r;
}
__device__ __forceinline__ void st_cluster_f32(void* local_ptr, uint32_t target_rank, float v) {
    uint32_t a = (uint32_t)__cvta_generic_to_shared(local_ptr);
    uint32_t remote;
    asm("mapa.shared::cluster.u32 %0, %1, %2;" : "=r"(remote) : "r"(a), "r"(target_rank));
    asm volatile("st.shared::cluster.f32 [%0], %1;" :: "r"(remote), "f"(v) : "memory");
}
__device__ __forceinline__ void cluster_sync_() {
    asm volatile("barrier.cluster.arrive.aligned;" ::: "memory");
    asm volatile("barrier.cluster.wait.aligned;"   ::: "memory");
}

__global__ __launch_bounds__(T, 1) __cluster_dims__(NC, 1, 1)
void nll_cluster(const float4* __restrict__ pred4,
                 const float4* __restrict__ label4,
                 float* __restrict__ out, int out_size) {
    const int t = threadIdx.x;
    const unsigned lane = t & 31u;
    const unsigned wid  = t >> 5;
    const uint32_t rank = ctarank();

    __shared__ float s_warp[NWARP];     // warp scan totals
    __shared__ float s_ctatot[NC];      // peer CTA totals (written by peers)
    __shared__ float s_redc[NC];        // final reduce: contributions (CTA0)
    __shared__ float s_redn[NC];        // final reduce: counts (CTA0)
    __shared__ float s_rs[NWARP], s_rc[NWARP];

    // ---------------- all loads issued up front (MLP = 6) -------------------
    const int g = (int)rank * T + t;    // thread rank across cluster
    float4 pa = pred4[g * 2 + 0];
    float4 pb = pred4[g * 2 + 1];
    float4 l0 = label4[g * 4 + 0];
    float4 l1 = label4[g * 4 + 1];
    float4 l2 = label4[g * 4 + 2];
    float4 l3 = label4[g * 4 + 3];

    float p[VPT] = {pa.x, pa.y, pa.z, pa.w, pb.x, pb.y, pb.z, pb.w};
    float ev[VPT] = {l0.y, l0.w, l1.y, l1.w, l2.y, l2.w, l3.y, l3.w};

    // ---------------- exp (MUFU, independent) + local inclusive scan --------
    float e[VPT], r[VPT];
    #pragma unroll
    for (int k = 0; k < VPT; k++) e[k] = __expf(p[k]);
    {
        float run = 0.f;
        #pragma unroll
        for (int k = 0; k < VPT; k++) { run += e[k]; r[k] = run; }
    }
    const float tot = r[VPT - 1];

    // ---------------- CTA-wide exclusive prefix of thread totals ------------
    float ws = tot;
    #pragma unroll
    for (int o = 1; o < 32; o <<= 1) {
        float n = __shfl_up_sync(0xffffffffu, ws, o);
        if (lane >= (unsigned)o) ws += n;
    }
    if (lane == 31) s_warp[wid] = ws;
    __syncthreads();
    if (wid == 0 && lane < NWARP) {
        float w = s_warp[lane];
        #pragma unroll
        for (int o = 1; o < NWARP; o <<= 1) {
            float n = __shfl_up_sync(0x000000ffu, w, o);
            if (lane >= (unsigned)o) w += n;
        }
        s_warp[lane] = w;
    }
    __syncthreads();
    const float P = (wid ? s_warp[wid - 1] : 0.f) + (ws - tot);
    const float ctaTotal = s_warp[NWARP - 1];

    // ---------------- exchange CTA totals across cluster --------------------
    if (t < NC) st_cluster_f32(&s_ctatot[rank], (uint32_t)t, ctaTotal);
    cluster_sync_();

    float ctaExcl = 0.f;
    #pragma unroll
    for (int j = 0; j < NC; j++)
        if ((unsigned)j < rank) ctaExcl += s_ctatot[j];

    // ---------------- masked contributions (fast log) -----------------------
    const float base = ctaExcl + P;
    float c = 0.f, cnt = 0.f;
    #pragma unroll
    for (int k = 0; k < VPT; k++) {
        if (ev[k] != 0.f) {
            c   += ev[k] * (p[k] - __logf(base + r[k]));
            cnt += ev[k];
        }
    }

    // ---------------- CTA reduce (c, cnt) -----------------------------------
    #pragma unroll
    for (int o = 16; o > 0; o >>= 1) {
        c   += __shfl_down_sync(0xffffffffu, c, o);
        cnt += __shfl_down_sync(0xffffffffu, cnt, o);
    }
    if (lane == 0) { s_rs[wid] = c; s_rc[wid] = cnt; }
    __syncthreads();
    if (t == 0) {
        float bc = 0.f, bn = 0.f;
        #pragma unroll
        for (int w = 0; w < NWARP; w++) { bc += s_rs[w]; bn += s_rc[w]; }
        st_cluster_f32(&s_redc[rank], 0u, bc);
        st_cluster_f32(&s_redn[rank], 0u, bn);
    }
    cluster_sync_();

    if (rank == 0 && t == 0) {
        float cs = 0.f, ys = 0.f;
        #pragma unroll
        for (int j = 0; j < NC; j++) { cs += s_redc[j]; ys += s_redn[j]; }
        float cost = (ys == 0.f) ? 0.f : -(cs / fmaxf(ys, 1.f));
        out[0] = cost;
        if (out_size > 1) out[1] = ys;
    }
}

extern "C" void kernel_launch(void* const* d_in, const int* in_sizes, int n_in,
                              void* d_out, int out_size) {
    const float4* pred4  = (const float4*)d_in[0];
    const float4* label4 = (const float4*)d_in[1];
    float* out = (float*)d_out;

    nll_cluster<<<NC, T>>>(pred4, label4, out, out_size);
}